// round 13
// baseline (speedup 1.0000x reference)
#include <cuda_runtime.h>
#include <cuda_fp16.h>
#include <cstdint>

#define IN_DIM   4096
#define OUT_DIM  16384
#define MDIM     32

#define NTILE    32             // output cols per CTA -> grid 512
#define KC       64             // K per chunk
#define NCHUNK   (IN_DIM / KC)  // 64
#define NST_A    4              // A ring (8KB SW128 stages)
#define K_PER_MMA 16
#define MMA_M    128
#define MMA_IDESC ((1u<<4) | ((NTILE/8)<<17) | ((MMA_M/16)<<24))   // f32 acc, f16 in

#define NTHREADS 288            // 8 producer warps + 1 MMA warp

// ---- dynamic smem layout (bytes)
#define SM_TMEMPTR 0
#define SM_MBAR(s) (8 + 8*(s))                    // 0..3: mma commit, 4..5: full
#define SM_A(s)    (1024 + (s)*8192)              // 4 x 8KB fp16 A
#define SM_BF(s)   (33792 + (s)*4096)             // 2 x 4KB fp16 B (32 rows x 128B)
#define SMEM_TOTAL 43008                          // ~42KB -> 3 CTAs/SM
// epilogue scratch reuses A region after drain
#define EP_OFF     1024                           // [32][33] floats
#define YS_OFF     (1024 + 4352)                  // [32][36] floats

// arch-specific gate: tcgen05 only exists in the sm_103a-specific target.
#if defined(__CUDA_ARCH_FEAT_SM103_ALL) || defined(__CUDA_ARCH_FEAT_SM100_ALL) || \
    defined(__CUDA_ARCH_FEAT_SM101_ALL) || \
    (defined(__CUDA_ARCH_SPECIFIC__)) || (defined(__CUDA_ARCH_FAMILY_SPECIFIC__))
#define TC_OK 1
#else
#define TC_OK 0
#endif

// pre-converted A: rows 0..31 = hi(x), rows 32..63 = lo(x), fp16, row-major [64][4096]
__device__ __align__(1024) __half g_A[64 * IN_DIM];

#define SW128(o) ((o) ^ (((o) >> 3) & 0x70))

#if TC_OK
__device__ __forceinline__ uint32_t elect1() {
    uint32_t p;
    asm volatile("{\n\t.reg .pred p;\n\telect.sync _|p, 0xFFFFFFFF;\n\tselp.b32 %0, 1, 0, p;\n\t}" : "=r"(p));
    return p;
}

__device__ __forceinline__ void mma_f16_ss(uint32_t d_tmem, uint64_t a_desc,
                                           uint64_t b_desc, uint32_t idesc, uint32_t en) {
    asm volatile(
        "{\n\t.reg .pred p;\n\tsetp.ne.u32 p, %4, 0;\n\t"
        "tcgen05.mma.cta_group::1.kind::f16 [%0], %1, %2, %3, {%5, %5, %5, %5}, p;\n\t}"
        :: "r"(d_tmem), "l"(a_desc), "l"(b_desc), "r"(idesc), "r"(en), "r"(0u)
        : "memory");
}

// K-major SW128 smem descriptor (LBO=1, SBO=64, version=1, layout=SW128)
__device__ __forceinline__ uint64_t mk_desc(uint32_t saddr) {
    return ((uint64_t)2 << 61) | ((uint64_t)1 << 46) | ((uint64_t)64 << 32)
         | ((uint64_t)1 << 16) | ((uint64_t)(saddr >> 4) & 0x3FFF);
}

__device__ __forceinline__ void mbar_wait(uint32_t mb, int phase) {
    uint32_t done;
    asm volatile(
        "{\n\t.reg .pred p;\n\t"
        "mbarrier.try_wait.parity.acquire.cta.shared::cta.b64 p, [%1], %2;\n\t"
        "selp.b32 %0, 1, 0, p;\n\t}" : "=r"(done) : "r"(mb), "r"(phase) : "memory");
    if (!done) {
        asm volatile(
            "{\n\t.reg .pred P1;\n\tW0_%=:\n\t"
            "mbarrier.try_wait.parity.acquire.cta.shared::cta.b64 P1, [%0], %1, 0x989680;\n\t"
            "@P1 bra.uni W1_%=;\n\tbra.uni W0_%=;\n\tW1_%=:\n\t}"
            :: "r"(mb), "r"(phase) : "memory");
    }
}

__device__ __forceinline__ void cp16(uint32_t dst, const void* src) {
    asm volatile("cp.async.cg.shared.global [%0], [%1], 16;"
                 :: "r"(dst), "l"(src) : "memory");
}

// pack two int codes (0..255, high bytes zero) -> fp16x2 (q+1024), then subtract (1024+zero)
__device__ __forceinline__ uint32_t pack2(uint32_t a, uint32_t b, uint32_t hz2) {
    uint32_t r;
    asm("prmt.b32 %0, %1, %2, 0x5410;" : "=r"(r) : "r"(a), "r"(b));
    r += 0x64006400u;
    uint32_t o;
    asm("add.f16x2 %0, %1, %2;" : "=r"(o) : "r"(r), "r"(hz2));
    return o;
}
#endif

__global__ void xsplit_kernel(const float* __restrict__ x) {
    int i = blockIdx.x * blockDim.x + threadIdx.x;   // 0 .. 32*4096-1
    if (i >= MDIM * IN_DIM) return;
    float v  = x[i];
    __half h = __float2half_rn(v);
    __half l = __float2half_rn(v - __half2float(h));
    int m = i / IN_DIM, k = i % IN_DIM;
    g_A[m * IN_DIM + k]        = h;
    g_A[(m + 32) * IN_DIM + k] = l;
}

__global__ __launch_bounds__(NTHREADS, 3)
void qgemm_tc(const int* __restrict__ wq,
              const int* __restrict__ zerop,
              const float* __restrict__ scalep,
              const float* __restrict__ bias,
              float* __restrict__ out)
{
#if TC_OK
    extern __shared__ char smem[];
    const uint32_t sb = (uint32_t)__cvta_generic_to_shared(smem);
    const int t   = threadIdx.x;
    const int wid = t >> 5;
    const int lid = t & 31;
    const int o0  = blockIdx.x * NTILE;

    const int zero = zerop[0];
    const __half  hzh = __int2half_rn(-1024 - zero);
    const __half2 hzv = __halves2half2(hzh, hzh);
    const uint32_t hz2 = *(const uint32_t*)&hzv;

    if (wid == 0) {
        asm volatile("tcgen05.alloc.cta_group::1.sync.aligned.shared::cta.b32 [%0], %1;"
                     :: "r"(sb + SM_TMEMPTR), "r"(32u) : "memory");
        asm volatile("tcgen05.relinquish_alloc_permit.cta_group::1.sync.aligned;");
    }
    if (t == 0) {
#pragma unroll
        for (int s = 0; s < 4; s++)    // mma-commit mbars, count 1
            asm volatile("mbarrier.init.shared.b64 [%0], 1;" :: "r"(sb + SM_MBAR(s)) : "memory");
#pragma unroll
        for (int s = 4; s < 6; s++)    // full mbars, count 8 (one per producer warp)
            asm volatile("mbarrier.init.shared.b64 [%0], 8;" :: "r"(sb + SM_MBAR(s)) : "memory");
    }
    __syncthreads();
    uint32_t tmem;
    asm volatile("ld.shared.b32 %0, [%1];" : "=r"(tmem) : "r"(sb + SM_TMEMPTR));

    if (wid < 8) {
        // ================= PRODUCER WARPS =================
        // B: row r = t>>3 (0..31), seg = t&7 (8 ints = 32B); 2x LDG.128 per chunk
        const int brow = t >> 3, bseg = t & 7;
        const int4* bsrc = (const int4*)(wq + (size_t)(o0 + brow) * IN_DIM + bseg * 8);
        const uint32_t b_sw = SW128((uint32_t)(brow * 128 + bseg * 16));
        // A: row ar = t>>2 (0..63), seg as = t&3 (32B); 2x16B cp.async, SW128
        const int ar = t >> 2, as = t & 3;
        const char* asrc = (const char*)g_A + (size_t)ar * IN_DIM * 2 + as * 32;
        const uint32_t a_sw0 = SW128((uint32_t)(ar*128 + as*32));
        const uint32_t a_sw1 = SW128((uint32_t)(ar*128 + as*32 + 16));

        // register prefetch ring, fixed rotation (distance 2)
        int4 q0a, q0b, q1a, q1b;

#define LDGB(dst_a, dst_b, c)                                                     \
    do {                                                                          \
        dst_a = __ldcs(bsrc + (size_t)(c) * (KC / 4));                            \
        dst_b = __ldcs(bsrc + (size_t)(c) * (KC / 4) + 1);                        \
    } while (0)

#define CPA(c)                                                                    \
    do {                                                                          \
        const uint32_t atile = sb + SM_A((c) & (NST_A - 1));                      \
        cp16(atile + a_sw0, asrc + (size_t)(c) * 128);                            \
        cp16(atile + a_sw1, asrc + (size_t)(c) * 128 + 16);                       \
        asm volatile("cp.async.commit_group;" ::: "memory");                      \
    } while (0)

        int ph[4] = {0, 0, 0, 0};

        LDGB(q0a, q0b, 0); CPA(0);
        LDGB(q1a, q1b, 1); CPA(1);

        for (int c = 0; c < NCHUNK; c++) {
            // gate bf(c&1) + A-ring reuse on MMA(c-2) completion
            if (c >= 2) {
                const int b = (c - 2) & 3;
                mbar_wait(sb + SM_MBAR(b), ph[b]);
                ph[b] ^= 1;
            }

            // consume (q0a,q0b) = chunk c's B data; refill for chunk c+2
            int4 qa = q0a, qb = q0b;
            if (c + 2 < NCHUNK) { LDGB(q0a, q0b, c + 2); CPA(c + 2); }
            // rotate: next iteration consumes what's now in q0
            { int4 ta = q0a, tb = q0b; q0a = q1a; q0b = q1b; q1a = ta; q1b = tb; }

            // A(c) landed (A-only groups; up to 2 newer pending)
            if (c + 2 < NCHUNK)
                asm volatile("cp.async.wait_group 2;" ::: "memory");
            else if (c + 1 < NCHUNK)
                asm volatile("cp.async.wait_group 1;" ::: "memory");
            else
                asm volatile("cp.async.wait_group 0;" ::: "memory");

            // convert chunk c's registers -> fp16 B tile (SW128)
            {
                const uint32_t bf = sb + SM_BF(c & 1);
                uint32_t h0 = pack2((uint32_t)qa.x, (uint32_t)qa.y, hz2);
                uint32_t h1 = pack2((uint32_t)qa.z, (uint32_t)qa.w, hz2);
                uint32_t h2 = pack2((uint32_t)qb.x, (uint32_t)qb.y, hz2);
                uint32_t h3 = pack2((uint32_t)qb.z, (uint32_t)qb.w, hz2);
                asm volatile("st.shared.v4.b32 [%0], {%1,%2,%3,%4};"
                    :: "r"(bf + b_sw), "r"(h0), "r"(h1), "r"(h2), "r"(h3) : "memory");
            }

            // signal: this warp's slice of chunk c (B converted + A cp.async complete)
            asm volatile("fence.proxy.async.shared::cta;" ::: "memory");
            __syncwarp();
            if (elect1())
                asm volatile("mbarrier.arrive.shared.b64 _, [%0];"
                             :: "r"(sb + SM_MBAR(4 + (c & 1))) : "memory");
            // straight to chunk c+1 — no peer/MMA-issue waiting
        }

        // drain: MMAs of chunks 62, 63 (needed before epilogue TMEM read)
        {
            const int bA = (NCHUNK - 2) & 3;
            mbar_wait(sb + SM_MBAR(bA), ph[bA]);
            const int bB = (NCHUNK - 1) & 3;
            mbar_wait(sb + SM_MBAR(bB), ph[bB]);
        }
        asm volatile("tcgen05.fence::after_thread_sync;" ::: "memory");
    } else {
        // ================= MMA WARP (wid == 8) =================
        int phf[2] = {0, 0};
        for (int c = 0; c < NCHUNK; c++) {
            const int f = c & 1;
            mbar_wait(sb + SM_MBAR(4 + f), phf[f]);
            phf[f] ^= 1;
            if (elect1()) {
                // A desc footprint rows 64..127 read junk (next region) -> only
                // pollutes D rows 64..127, never read out.
                uint64_t ad = mk_desc(sb + SM_A(c & (NST_A - 1)));
                uint64_t bd = mk_desc(sb + SM_BF(f));
#pragma unroll
                for (int s = 0; s < KC / K_PER_MMA; s++)
                    mma_f16_ss(tmem, ad + s * 2, bd + s * 2, MMA_IDESC,
                               (c > 0 || s > 0) ? 1u : 0u);
                asm volatile(
                    "tcgen05.commit.cta_group::1.mbarrier::arrive::one.shared::cluster.b64 [%0];"
                    :: "r"(sb + SM_MBAR(c & 3)) : "memory");
            }
        }
    }

    __syncthreads();   // converge all 9 warps; A region reused as epilogue scratch

    // ---- epilogue: warp0 holds hi rows (m=lid), warp1 holds lo rows
    const float scale = scalep[0];
    float* Ep = (float*)(smem + EP_OFF);     // [32][33]
    float* Ys = (float*)(smem + YS_OFF);     // [32][36]

    {
        uint32_t d[32];
        if (wid < 2) {
            asm volatile(
                "tcgen05.ld.sync.aligned.32x32b.x32.b32 "
                "{%0,%1,%2,%3,%4,%5,%6,%7,%8,%9,%10,%11,%12,%13,%14,%15,"
                "%16,%17,%18,%19,%20,%21,%22,%23,%24,%25,%26,%27,%28,%29,%30,%31}, [%32];"
                : "=r"(d[0]), "=r"(d[1]), "=r"(d[2]), "=r"(d[3]), "=r"(d[4]), "=r"(d[5]),
                  "=r"(d[6]), "=r"(d[7]), "=r"(d[8]), "=r"(d[9]), "=r"(d[10]), "=r"(d[11]),
                  "=r"(d[12]), "=r"(d[13]), "=r"(d[14]), "=r"(d[15]), "=r"(d[16]), "=r"(d[17]),
                  "=r"(d[18]), "=r"(d[19]), "=r"(d[20]), "=r"(d[21]), "=r"(d[22]), "=r"(d[23]),
                  "=r"(d[24]), "=r"(d[25]), "=r"(d[26]), "=r"(d[27]), "=r"(d[28]), "=r"(d[29]),
                  "=r"(d[30]), "=r"(d[31])
                : "r"(tmem));
            asm volatile("tcgen05.wait::ld.sync.aligned;" ::: "memory");
        }
        if (wid == 1) {
#pragma unroll
            for (int cc = 0; cc < 32; cc++) Ep[lid * 33 + cc] = __uint_as_float(d[cc]);
        }
        __syncthreads();
        if (wid == 0) {
#pragma unroll
            for (int cc = 0; cc < 32; cc++) {
                float hi = __uint_as_float(d[cc]);
                float lo = Ep[lid * 33 + cc];
                float b  = bias[o0 + cc];
                Ys[lid * 36 + cc] = fmaf(scale, hi + lo, b);
            }
        }
        __syncthreads();
    }

    // ---- coalesced store: 32 rows x 32 cols (first 256 threads)
    if (t < 256) {
        const int m = t >> 3, q = t & 7;
        float4 v = *(const float4*)(Ys + m * 36 + q * 4);
        *(float4*)(out + (size_t)m * OUT_DIM + o0 + q * 4) = v;
    }

    __syncthreads();
    if (t == 0) {
#pragma unroll
        for (int s = 0; s < 6; s++)
            asm volatile("mbarrier.inval.shared.b64 [%0];" :: "r"(sb + SM_MBAR(s)) : "memory");
    }
    __syncthreads();
    if (wid == 0) {
        asm volatile("tcgen05.dealloc.cta_group::1.sync.aligned.b32 %0, %1;"
                     :: "r"(tmem), "r"(32u));
    }
#endif  // TC_OK
}

extern "C" void kernel_launch(void* const* d_in, const int* in_sizes, int n_in,
                              void* d_out, int out_size)
{
    const float* x     = (const float*)d_in[0];
    const int*   wq    = (const int*)  d_in[1];
    const int*   zero  = (const int*)  d_in[2];
    const float* scale = (const float*)d_in[3];
    const float* bias  = (const float*)d_in[4];
    float*       out   = (float*)d_out;

    cudaFuncSetAttribute(qgemm_tc, cudaFuncAttributeMaxDynamicSharedMemorySize, SMEM_TOTAL);

    xsplit_kernel<<<(MDIM * IN_DIM + 255) / 256, 256>>>(x);
    qgemm_tc<<<OUT_DIM / NTILE, NTHREADS, SMEM_TOTAL>>>(wq, zero, scale, bias, out);
}